// round 11
// baseline (speedup 1.0000x reference)
#include <cuda_runtime.h>
#include <math.h>

#define Hs 512
#define Ws 512
#define HW (Hs * Ws)
#define Bn 128
#define NRING 256          // only rings 4..255 matter for the output
#define PAIRS 128          // ring pairs (rings 0..255)
#define TR 8               // tile rows
#define TC 32              // tile cols (full 128B lines per batch row)
#define TILES_X (Ws / TC)  // 16
#define NTILES 1024
#define WIN 36             // ring window: w_max <= 35 proven (diag 32.98+2.5)
#define PITCH2 36          // staging words per batch row (16B aligned, cf-free)

// Global scratch (static device arrays — no allocation).
// g_S4[b*PAIRS + p] = (S1[2p], S2[2p], S1[2p+1], S2[2p+1]) for batch b.
__device__ float4 g_S4[Bn * PAIRS];
__device__ int    g_icnt[NRING];
__device__ int    g_done;

// ---------------------------------------------------------------------------
// Zero ALL cross-call scratch every launch (graph-replay determinism).
// ---------------------------------------------------------------------------
__global__ void zero_kernel() {
    int i = blockIdx.x * blockDim.x + threadIdx.x;   // 32 x 128 = 4096
    float4 z = make_float4(0.f, 0.f, 0.f, 0.f);
    #pragma unroll
    for (int k = 0; k < 4; ++k) g_S4[i + k * 4096] = z;
    if (i < NRING) g_icnt[i] = 0;
    if (i == 0) g_done = 0;
}

// No-op launches so ncu (profiles launch index 3) lands on pass1.
__global__ void noop_kernel() {}

// ---------------------------------------------------------------------------
// Pass 1: r7's measured-best streaming pipeline (thread = batch, smem
// transpose, depth-2 LDG register prefetch, double-buffered dv staging,
// 12 warps/SM), plus fused ring counting and fused last-block reduction.
// Rings computed arithmetically (exact vs np.round: r^2 is an exact fp32
// integer, sqrt correctly rounded, half-way cases impossible).
// ---------------------------------------------------------------------------
__global__ __launch_bounds__(128, 3) void pass1_kernel(
    const float* __restrict__ parts, const float* __restrict__ projs,
    float* __restrict__ out) {
    __shared__ float2 acc[WIN * Bn];              // 36864 B
    __shared__ float  nbuf[2 * Bn * PITCH2];      // 36864 B
    __shared__ int    rbuf[2 * TC];
    __shared__ int    icnt[WIN];
    __shared__ int    lastFlag;

    const int t = threadIdx.x;            // t == batch index
    const int tile = blockIdx.x;
    const int ty = tile >> 4, tx = tile & 15;
    const int i0 = ty * TR, j0 = tx * TC;

    // Exact lower bound of ring over the tile rect (center = (256,256)).
    float dI = (i0 > 256) ? (float)(i0 - 256)
             : ((i0 + TR - 1) < 256 ? (float)(256 - (i0 + TR - 1)) : 0.f);
    float dJ = (j0 > 256) ? (float)(j0 - 256)
             : ((j0 + TC - 1) < 256 ? (float)(256 - (j0 + TC - 1)) : 0.f);
    const int rbase = (int)floorf(__fsqrt_rn(dI * dI + dJ * dJ));
    const bool active = (rbase < NRING);   // block-uniform
    const int rbase2 = rbase & ~1;         // even-aligned window base

    if (active) {
        #pragma unroll
        for (int k = 0; k < WIN; ++k) acc[k * Bn + t] = make_float2(0.f, 0.f);
        if (t < WIN) icnt[t] = 0;

        const int sub = t & 7;   // float4 slot along px (px0 = sub*4)
        const int bg  = t >> 3;  // batch-group 0..15
        float4 p[8], q[8], dv[8];

        auto ld = [&](int s) {
            const int rowoff = (i0 + s) * Ws + j0 + sub * 4;
            #pragma unroll
            for (int r = 0; r < 8; ++r) {
                int b = r * 16 + bg;
                p[r] = __ldcs((const float4*)(parts + (size_t)b * HW + rowoff));
                q[r] = __ldcs((const float4*)(projs + (size_t)b * HW + rowoff));
            }
        };
        auto sub_pq = [&]() {
            #pragma unroll
            for (int r = 0; r < 8; ++r)
                dv[r] = make_float4(p[r].x - q[r].x, p[r].y - q[r].y,
                                    p[r].z - q[r].z, p[r].w - q[r].w);
        };

        ld(0);
        sub_pq();
        ld(1);

        float s1 = 0.f, s2 = 0.f;
        int cur = -1;

        for (int s = 0; s < TR; ++s) {
            float* nb = nbuf + (s & 1) * (Bn * PITCH2);
            // STS stage s (vector): nb[b][sub*4..+3] = dv
            #pragma unroll
            for (int r = 0; r < 8; ++r) {
                int b = r * 16 + bg;
                *(float4*)(nb + b * PITCH2 + sub * 4) = dv[r];
            }
            if (t < TC) {   // ring row for stage s (broadcast-read later)
                float di = (float)(i0 + s - 256);
                float dj = (float)(j0 + t - 256);
                rbuf[(s & 1) * TC + t] =
                    __float2int_rn(__fsqrt_rn(fmaf(di, di, dj * dj))) - rbase2;
            }
            if (s + 1 < TR) sub_pq();   // convert stage s+1 (arrived earlier)
            if (s + 2 < TR) ld(s + 2);  // refill freed p/q regs (depth-2)
            __syncthreads();            // STS(s)+rbuf visible
            // Compute stage s: thread t = batch t, 8 quads of 4 pixels
            const float* nr = nb + t * PITCH2;
            const int*   rr = rbuf + (s & 1) * TC;
            #pragma unroll
            for (int qd = 0; qd < 8; ++qd) {
                float4 d4 = *(const float4*)(nr + qd * 4);
                int4   r4 = *(const int4*)(rr + qd * 4);
                #pragma unroll
                for (int e = 0; e < 4; ++e) {
                    float d = e == 0 ? d4.x : e == 1 ? d4.y : e == 2 ? d4.z : d4.w;
                    int   w = e == 0 ? r4.x : e == 1 ? r4.y : e == 2 ? r4.z : r4.w;
                    if (w != cur) {   // warp-uniform
                        if (cur >= 0) {
                            float2 a = acc[cur * Bn + t];
                            a.x += s1; a.y += s2;
                            acc[cur * Bn + t] = a;
                        }
                        cur = w; s1 = 0.f; s2 = 0.f;
                    }
                    s1 += fabsf(d);
                    s2 = fmaf(d, d, s2);
                }
            }
        }
        if (cur >= 0) {
            float2 a = acc[cur * Bn + t];
            a.x += s1; a.y += s2;
            acc[cur * Bn + t] = a;
        }
        // Fused ring-pixel counting: lane t<32 counts its column's 8 rows.
        if (t < TC) {
            float dj = (float)(j0 + t - 256);
            #pragma unroll
            for (int r = 0; r < TR; ++r) {
                float di = (float)(i0 + r - 256);
                int ring = __float2int_rn(__fsqrt_rn(fmaf(di, di, dj * dj)));
                atomicAdd(&icnt[ring - rbase2], 1);
            }
        }
        __syncthreads();

        // Merge stats: two rings per red.global.add.v4.f32, clipped to [4,256).
        const int p0 = (rbase2 > 4) ? rbase2 : 4;                      // even
        const int p1 = (rbase2 + WIN < NRING) ? rbase2 + WIN : NRING;  // excl
        for (int ring = p0; ring < p1; ring += 2) {
            int w = ring - rbase2;
            float2 a0 = acc[w * Bn + t];
            float2 a1 = acc[(w + 1) * Bn + t];
            if (a0.x != 0.f || a1.x != 0.f) {
                float4* ptr = &g_S4[t * PAIRS + (ring >> 1)];
                asm volatile("red.global.add.v4.f32 [%0], {%1, %2, %3, %4};"
                             :: "l"(ptr), "f"(a0.x), "f"(a0.y),
                                "f"(a1.x), "f"(a1.y)
                             : "memory");
            }
        }
        // Merge counts (int, exactly deterministic).
        if (t < WIN) {
            int ring = rbase2 + t;
            if (ring > 3 && ring < NRING && icnt[t])
                atomicAdd(&g_icnt[ring], icnt[t]);
        }
    }

    // ---- last-block fused reduction (threadFenceReduction pattern) ----
    __threadfence();
    __syncthreads();
    if (t == 0) lastFlag = (atomicAdd(&g_done, 1) == NTILES - 1);
    __syncthreads();
    if (lastFlag) {
        // thread t = batch t; pairs 2..127 = rings 4..255
        float sum = 0.f;
        #pragma unroll 4
        for (int pp = 2; pp < PAIRS; ++pp) {
            float4 v = g_S4[t * PAIRS + pp];
            #pragma unroll
            for (int h = 0; h < 2; ++h) {
                float c   = (float)g_icnt[2 * pp + h];
                float s1v = h ? v.z : v.x;
                float s2v = h ? v.w : v.y;
                float mean = s1v / fmaxf(c, 1.f);
                float ssq  = s2v - c * mean * mean;
                float var  = ssq / fmaxf(c - 1.f, 1.f);
                sum += -0.5f * s2v / var - c * __logf(6.283185307179586f * var);
            }
        }
        out[t] = sum;
    }
}

// ---------------------------------------------------------------------------
extern "C" void kernel_launch(void* const* d_in, const int* in_sizes, int n_in,
                              void* d_out, int out_size) {
    const float* parts = (const float*)d_in[0];
    const float* projs = (const float*)d_in[1];
    // d_in[2] (bins) unused: rings recomputed exactly (matches np.round).
    // d_in[3] (valid_mask) unused: mask == (3 < bin < 256), folded analytically.
    float* out = (float*)d_out;

    zero_kernel<<<32, 128>>>();                               // launch 0
    noop_kernel<<<1, 32>>>();                                 // launch 1
    noop_kernel<<<1, 32>>>();                                 // launch 2
    pass1_kernel<<<NTILES, 128>>>(parts, projs, out);         // launch 3 <- ncu
}

// round 12
// speedup vs baseline: 1.6336x; 1.6336x over previous
#include <cuda_runtime.h>
#include <math.h>

#define Hs 512
#define Ws 512
#define HW (Hs * Ws)
#define Bn 128
#define NRING 256          // only rings 4..255 matter for the output
#define PAIRS 128          // ring pairs (rings 0..255)
#define TR 8               // tile rows
#define TC 32              // tile cols (full 128B lines per batch row)
#define NTILES 1024
#define WIN 36             // ring window: w_max <= 35 proven (diag 32.98 + 2.5)
#define PITCH2 36          // staging words per batch row (16B aligned, cf-free)

// Global scratch (static device arrays — no allocation).
// g_S4[b*PAIRS + p] = (S1[2p], S2[2p], S1[2p+1], S2[2p+1]) for batch b.
// g_S4 starts zero (module load) and is self-cleaned by pass3 every call.
__device__ float4 g_S4[Bn * PAIRS];
__device__ int    g_icnt[NRING];

// ---------------------------------------------------------------------------
// Zero the per-call count scratch (tiny; g_S4 is self-cleaned by pass3).
// ---------------------------------------------------------------------------
__global__ void zero_kernel() {
    g_icnt[threadIdx.x] = 0;
}

// No-op; padding so ncu (profiles launch index 3) lands on pass1.
__global__ void noop_kernel() {}

// ---------------------------------------------------------------------------
// Pass 1: r7's measured-best streaming pipeline (thread = batch, smem
// transpose, depth-2 LDG register prefetch, double-buffered dv staging,
// one __syncthreads per stage, 12 warps/SM) + fused ring-pixel counting.
// NO threadfence / ticket anywhere (r8-r11 plateau attributed to per-block
// gpu-scope fence -> CCTL.IVALL L1 flush + pipe drain).
// Rings computed arithmetically (exact vs np.round: r^2 is an exact fp32
// integer, sqrt correctly rounded, half-way cases impossible).
// ---------------------------------------------------------------------------
__global__ __launch_bounds__(128, 3) void pass1_kernel(
    const float* __restrict__ parts, const float* __restrict__ projs) {
    extern __shared__ char smraw[];
    float2* acc  = (float2*)smraw;                                   // WIN*128
    float*  nbuf = (float*)(smraw + WIN * Bn * sizeof(float2));      // 2*Bn*PITCH2
    int*    rbuf = (int*)(smraw + WIN * Bn * sizeof(float2)
                                + 2 * Bn * PITCH2 * sizeof(float));  // 2*TC
    int*    icnt = rbuf + 2 * TC;                                    // WIN

    const int t = threadIdx.x;            // t == batch index
    const int tile = blockIdx.x;
    const int ty = tile >> 4, tx = tile & 15;
    const int i0 = ty * TR, j0 = tx * TC;

    // Exact lower bound of ring over the tile rect (center = (256,256)).
    float dI = (i0 > 256) ? (float)(i0 - 256)
             : ((i0 + TR - 1) < 256 ? (float)(256 - (i0 + TR - 1)) : 0.f);
    float dJ = (j0 > 256) ? (float)(j0 - 256)
             : ((j0 + TC - 1) < 256 ? (float)(256 - (j0 + TC - 1)) : 0.f);
    const int rbase = (int)floorf(__fsqrt_rn(dI * dI + dJ * dJ));
    if (rbase >= NRING) return;           // tile cannot affect the output
    const int rbase2 = rbase & ~1;        // even-aligned window base

    #pragma unroll
    for (int k = 0; k < WIN; ++k) acc[k * Bn + t] = make_float2(0.f, 0.f);
    if (t < WIN) icnt[t] = 0;

    const int sub = t & 7;   // float4 slot along px (px0 = sub*4)
    const int bg  = t >> 3;  // batch-group 0..15
    float4 p[8], q[8], dv[8];

    auto ld = [&](int s) {
        const int rowoff = (i0 + s) * Ws + j0 + sub * 4;
        #pragma unroll
        for (int r = 0; r < 8; ++r) {
            int b = r * 16 + bg;
            p[r] = __ldcs((const float4*)(parts + (size_t)b * HW + rowoff));
            q[r] = __ldcs((const float4*)(projs + (size_t)b * HW + rowoff));
        }
    };
    auto sub_pq = [&]() {
        #pragma unroll
        for (int r = 0; r < 8; ++r)
            dv[r] = make_float4(p[r].x - q[r].x, p[r].y - q[r].y,
                                p[r].z - q[r].z, p[r].w - q[r].w);
    };

    ld(0);
    sub_pq();
    ld(1);

    float s1 = 0.f, s2 = 0.f;
    int cur = -1;

    for (int s = 0; s < TR; ++s) {
        float* nb = nbuf + (s & 1) * (Bn * PITCH2);
        // STS stage s (vector): nb[b][sub*4..+3] = dv
        #pragma unroll
        for (int r = 0; r < 8; ++r) {
            int b = r * 16 + bg;
            *(float4*)(nb + b * PITCH2 + sub * 4) = dv[r];
        }
        if (t < TC) {   // ring row for stage s (broadcast-read later)
            float di = (float)(i0 + s - 256);
            float dj = (float)(j0 + t - 256);
            rbuf[(s & 1) * TC + t] =
                __float2int_rn(__fsqrt_rn(fmaf(di, di, dj * dj))) - rbase2;
        }
        if (s + 1 < TR) sub_pq();   // convert stage s+1 (arrived earlier)
        if (s + 2 < TR) ld(s + 2);  // refill freed p/q regs (depth-2 slack)
        __syncthreads();            // STS(s)+rbuf visible
        // Compute stage s: thread t = batch t, 8 quads of 4 pixels
        const float* nr = nb + t * PITCH2;
        const int*   rr = rbuf + (s & 1) * TC;
        #pragma unroll
        for (int qd = 0; qd < 8; ++qd) {
            float4 d4 = *(const float4*)(nr + qd * 4);
            int4   r4 = *(const int4*)(rr + qd * 4);
            #pragma unroll
            for (int e = 0; e < 4; ++e) {
                float d = e == 0 ? d4.x : e == 1 ? d4.y : e == 2 ? d4.z : d4.w;
                int   w = e == 0 ? r4.x : e == 1 ? r4.y : e == 2 ? r4.z : r4.w;
                if (w != cur) {   // warp-uniform
                    if (cur >= 0) {
                        float2 a = acc[cur * Bn + t];
                        a.x += s1; a.y += s2;
                        acc[cur * Bn + t] = a;
                    }
                    cur = w; s1 = 0.f; s2 = 0.f;
                }
                s1 += fabsf(d);
                s2 = fmaf(d, d, s2);
            }
        }
    }
    if (cur >= 0) {
        float2 a = acc[cur * Bn + t];
        a.x += s1; a.y += s2;
        acc[cur * Bn + t] = a;
    }
    // Fused ring-pixel counting: lane t<32 counts its column's 8 rows.
    if (t < TC) {
        float dj = (float)(j0 + t - 256);
        #pragma unroll
        for (int r = 0; r < TR; ++r) {
            float di = (float)(i0 + r - 256);
            int ring = __float2int_rn(__fsqrt_rn(fmaf(di, di, dj * dj)));
            atomicAdd(&icnt[ring - rbase2], 1);
        }
    }
    __syncthreads();

    // Merge stats: two rings per red.global.add.v4.f32, clipped to [4,256).
    const int p0 = (rbase2 > 4) ? rbase2 : 4;                      // even
    const int p1 = (rbase2 + WIN < NRING) ? rbase2 + WIN : NRING;  // exclusive
    for (int ring = p0; ring < p1; ring += 2) {
        int w = ring - rbase2;
        float2 a0 = acc[w * Bn + t];
        float2 a1 = acc[(w + 1) * Bn + t];
        if (a0.x != 0.f || a1.x != 0.f) {
            float4* ptr = &g_S4[t * PAIRS + (ring >> 1)];
            asm volatile("red.global.add.v4.f32 [%0], {%1, %2, %3, %4};"
                         :: "l"(ptr), "f"(a0.x), "f"(a0.y), "f"(a1.x), "f"(a1.y)
                         : "memory");
        }
    }
    // Merge counts (int, exactly deterministic).
    if (t < WIN) {
        int ring = rbase2 + t;
        if (ring > 3 && ring < NRING && icnt[t])
            atomicAdd(&g_icnt[ring], icnt[t]);
    }
}

// ---------------------------------------------------------------------------
// Pass 2 (separate kernel; launch boundary = ordering, no fence needed):
//   block b = batch b; thread = ring pair; block reduce.
//   logprob[b] = sum_r [ -0.5*S2/var - c*log(2*pi*var) ]
//   Self-cleans its own g_S4 slice for the next graph replay.
// ---------------------------------------------------------------------------
__global__ void pass3_kernel(float* __restrict__ out) {
    __shared__ float red[4];
    int b = blockIdx.x;
    int tid = threadIdx.x;
    float sum = 0.f;
    if (tid >= 2) {                      // pairs 2..127 = rings 4..255
        float4 v = g_S4[b * PAIRS + tid];
        g_S4[b * PAIRS + tid] = make_float4(0.f, 0.f, 0.f, 0.f);  // self-clean
        #pragma unroll
        for (int h = 0; h < 2; ++h) {
            float c   = (float)g_icnt[2 * tid + h];
            float s1v = h ? v.z : v.x;
            float s2v = h ? v.w : v.y;
            float mean = s1v / fmaxf(c, 1.f);
            float ssq  = s2v - c * mean * mean;
            float var  = ssq / fmaxf(c - 1.f, 1.f);
            sum += -0.5f * s2v / var - c * __logf(6.283185307179586f * var);
        }
    }
    #pragma unroll
    for (int off = 16; off > 0; off >>= 1)
        sum += __shfl_xor_sync(0xFFFFFFFFu, sum, off);
    if ((tid & 31) == 0) red[tid >> 5] = sum;
    __syncthreads();
    if (tid == 0) out[b] = red[0] + red[1] + red[2] + red[3];
}

// ---------------------------------------------------------------------------
extern "C" void kernel_launch(void* const* d_in, const int* in_sizes, int n_in,
                              void* d_out, int out_size) {
    const float* parts = (const float*)d_in[0];
    const float* projs = (const float*)d_in[1];
    // d_in[2] (bins) unused: rings recomputed exactly (matches np.round).
    // d_in[3] (valid_mask) unused: mask == (3 < bin < 256), folded analytically.
    float* out = (float*)d_out;

    const int smem = WIN * Bn * (int)sizeof(float2)
                   + 2 * Bn * PITCH2 * (int)sizeof(float)
                   + (2 * TC + WIN) * (int)sizeof(int);  // 74128 B
    cudaFuncSetAttribute(pass1_kernel,
                         cudaFuncAttributeMaxDynamicSharedMemorySize, smem);

    zero_kernel<<<1, NRING>>>();                          // launch 0
    noop_kernel<<<1, 32>>>();                             // launch 1
    noop_kernel<<<1, 32>>>();                             // launch 2
    pass1_kernel<<<NTILES, 128, smem>>>(parts, projs);    // launch 3 <- ncu
    pass3_kernel<<<Bn, 128>>>(out);                       // launch 4
}

// round 13
// speedup vs baseline: 2.1616x; 1.3232x over previous
#include <cuda_runtime.h>
#include <math.h>

#define Hs 512
#define Ws 512
#define HW (Hs * Ws)
#define Bn 128
#define NRING 256          // only rings 4..255 matter for the output
#define PAIRS 128          // ring pairs (rings 0..255)
#define TR 8               // tile rows
#define TC 32              // tile cols (full 128B lines per batch row)
#define NTILES 1024
#define WIN 36             // ring window: w_max <= 35 proven (diag 32.98 + 2.5)
#define BPITCH 36          // staging words per batch row (16B aligned, cf-free)

// Global scratch (static device arrays — no allocation).
// g_S4[b*PAIRS + p] = (S1[2p], S2[2p], S1[2p+1], S2[2p+1]) for batch b.
// g_S4 starts zero (module load) and is self-cleaned by pass3 every call.
__device__ float4 g_S4[Bn * PAIRS];
__device__ int    g_icnt[NRING];

// ---------------------------------------------------------------------------
__global__ void zero_kernel() {
    g_icnt[threadIdx.x] = 0;
}

// No-op; padding so ncu (profiles launch index 3) lands on pass1.
__global__ void noop_kernel() {}

// ---------------------------------------------------------------------------
// Pass 1: BARRIER-FREE hot loop. Warp w owns batches [32w, 32w+32) and stages
// ONLY its own batches into warp-private smem (single buffer, 2 __syncwarp
// per stage). Each of the 12 warps/SM free-runs its own depth-2 LDG pipeline,
// so latency-hiding granularity = 12 warps, not 3 lockstepped CTAs (r12's
// __syncthreads-per-stage welded each CTA's warps into one stall group).
// No threadfence anywhere (r8-r11 plateau == per-block gpu-scope fence).
// No occupancy forcing (r9's spills came from __launch_bounds__(128,4)).
// Rings computed arithmetically (exact vs np.round: r^2 is an exact fp32
// integer, sqrt correctly rounded, half-way cases impossible).
// ---------------------------------------------------------------------------
__global__ __launch_bounds__(128, 3) void pass1_kernel(
    const float* __restrict__ parts, const float* __restrict__ projs) {
    extern __shared__ char smraw[];
    float2* acc  = (float2*)smraw;                                   // WIN*128
    float*  stg  = (float*)(smraw + WIN * Bn * sizeof(float2));      // 4*32*BPITCH
    int*    rbuf = (int*)(smraw + WIN * Bn * sizeof(float2)
                                + 4 * 32 * BPITCH * sizeof(float));  // TR*TC
    int*    icnt = rbuf + TR * TC;                                   // WIN

    const int t = threadIdx.x;            // t == batch index
    const int warp = t >> 5, lane = t & 31;
    const int tile = blockIdx.x;
    const int ty = tile >> 4, tx = tile & 15;
    const int i0 = ty * TR, j0 = tx * TC;

    // Exact lower bound of ring over the tile rect (center = (256,256)).
    float dI = (i0 > 256) ? (float)(i0 - 256)
             : ((i0 + TR - 1) < 256 ? (float)(256 - (i0 + TR - 1)) : 0.f);
    float dJ = (j0 > 256) ? (float)(j0 - 256)
             : ((j0 + TC - 1) < 256 ? (float)(256 - (j0 + TC - 1)) : 0.f);
    const int rbase = (int)floorf(__fsqrt_rn(dI * dI + dJ * dJ));
    if (rbase >= NRING) return;           // tile cannot affect the output
    const int rbase2 = rbase & ~1;        // even-aligned window base

    #pragma unroll
    for (int k = 0; k < WIN; ++k) acc[k * Bn + t] = make_float2(0.f, 0.f);
    if (t < WIN) icnt[t] = 0;
    // Ring-offset table once per tile (shared by all stages).
    #pragma unroll
    for (int k = t; k < TR * TC; k += 128) {
        float di = (float)(i0 + (k >> 5) - 256);
        float dj = (float)(j0 + (k & 31) - 256);
        rbuf[k] = __float2int_rn(__fsqrt_rn(fmaf(di, di, dj * dj))) - rbase2;
    }
    __syncthreads();   // the ONLY block barrier before the epilogue

    float* nw = stg + warp * (32 * BPITCH);   // this warp's staging
    const int bbase = warp * 32;
    const int sub = lane & 7;   // float4 slot along px (px0 = sub*4)
    const int bgl = lane >> 3;  // local batch sub-group 0..3
    float4 p[8], q[8], dv[8];

    auto ld = [&](int s) {
        const int rowoff = (i0 + s) * Ws + j0 + sub * 4;
        #pragma unroll
        for (int k = 0; k < 8; ++k) {
            int b = bbase + k * 4 + bgl;
            p[k] = __ldcs((const float4*)(parts + (size_t)b * HW + rowoff));
            q[k] = __ldcs((const float4*)(projs + (size_t)b * HW + rowoff));
        }
    };
    auto sub_pq = [&]() {
        #pragma unroll
        for (int k = 0; k < 8; ++k)
            dv[k] = make_float4(p[k].x - q[k].x, p[k].y - q[k].y,
                                p[k].z - q[k].z, p[k].w - q[k].w);
    };

    ld(0);
    sub_pq();
    ld(1);

    float s1 = 0.f, s2 = 0.f;
    int cur = -1;

    for (int s = 0; s < TR; ++s) {
        // STS stage s (warp-private, vector)
        #pragma unroll
        for (int k = 0; k < 8; ++k)
            *(float4*)(nw + (k * 4 + bgl) * BPITCH + sub * 4) = dv[k];
        __syncwarp();
        if (s + 1 < TR) sub_pq();   // convert stage s+1 (arrived earlier)
        if (s + 2 < TR) ld(s + 2);  // refill freed p/q regs (depth-2 slack)
        // Compute stage s: thread t = batch t (local row = lane)
        const float* nr = nw + lane * BPITCH;
        const int*   rr = rbuf + s * TC;
        #pragma unroll
        for (int qd = 0; qd < 8; ++qd) {
            float4 d4 = *(const float4*)(nr + qd * 4);
            int4   r4 = *(const int4*)(rr + qd * 4);   // broadcast
            #pragma unroll
            for (int e = 0; e < 4; ++e) {
                float d = e == 0 ? d4.x : e == 1 ? d4.y : e == 2 ? d4.z : d4.w;
                int   w = e == 0 ? r4.x : e == 1 ? r4.y : e == 2 ? r4.z : r4.w;
                if (w != cur) {   // warp-uniform
                    if (cur >= 0) {
                        float2 a = acc[cur * Bn + t];
                        a.x += s1; a.y += s2;
                        acc[cur * Bn + t] = a;
                    }
                    cur = w; s1 = 0.f; s2 = 0.f;
                }
                s1 += fabsf(d);
                s2 = fmaf(d, d, s2);
            }
        }
        __syncwarp();   // all lanes done reading before next stage overwrites
    }
    if (cur >= 0) {
        float2 a = acc[cur * Bn + t];
        a.x += s1; a.y += s2;
        acc[cur * Bn + t] = a;
    }
    // Fused ring-pixel counting from the static table (shared atomics).
    #pragma unroll
    for (int k = t; k < TR * TC; k += 128) atomicAdd(&icnt[rbuf[k]], 1);
    __syncthreads();

    // Merge stats: two rings per red.global.add.v4.f32, clipped to [4,256).
    const int p0 = (rbase2 > 4) ? rbase2 : 4;                      // even
    const int p1 = (rbase2 + WIN < NRING) ? rbase2 + WIN : NRING;  // exclusive
    for (int ring = p0; ring < p1; ring += 2) {
        int w = ring - rbase2;
        float2 a0 = acc[w * Bn + t];
        float2 a1 = acc[(w + 1) * Bn + t];
        if (a0.x != 0.f || a1.x != 0.f) {
            float4* ptr = &g_S4[t * PAIRS + (ring >> 1)];
            asm volatile("red.global.add.v4.f32 [%0], {%1, %2, %3, %4};"
                         :: "l"(ptr), "f"(a0.x), "f"(a0.y), "f"(a1.x), "f"(a1.y)
                         : "memory");
        }
    }
    // Merge counts (int, exactly deterministic).
    if (t < WIN) {
        int ring = rbase2 + t;
        if (ring > 3 && ring < NRING && icnt[t])
            atomicAdd(&g_icnt[ring], icnt[t]);
    }
}

// ---------------------------------------------------------------------------
// Pass 2 (separate kernel; launch boundary = ordering, no fence needed):
//   block b = batch b; thread = ring pair; block reduce.
//   logprob[b] = sum_r [ -0.5*S2/var - c*log(2*pi*var) ]
//   Self-cleans its own g_S4 slice for the next graph replay.
// ---------------------------------------------------------------------------
__global__ void pass3_kernel(float* __restrict__ out) {
    __shared__ float red[4];
    int b = blockIdx.x;
    int tid = threadIdx.x;
    float sum = 0.f;
    if (tid >= 2) {                      // pairs 2..127 = rings 4..255
        float4 v = g_S4[b * PAIRS + tid];
        g_S4[b * PAIRS + tid] = make_float4(0.f, 0.f, 0.f, 0.f);  // self-clean
        #pragma unroll
        for (int h = 0; h < 2; ++h) {
            float c   = (float)g_icnt[2 * tid + h];
            float s1v = h ? v.z : v.x;
            float s2v = h ? v.w : v.y;
            float mean = s1v / fmaxf(c, 1.f);
            float ssq  = s2v - c * mean * mean;
            float var  = ssq / fmaxf(c - 1.f, 1.f);
            sum += -0.5f * s2v / var - c * __logf(6.283185307179586f * var);
        }
    }
    #pragma unroll
    for (int off = 16; off > 0; off >>= 1)
        sum += __shfl_xor_sync(0xFFFFFFFFu, sum, off);
    if ((tid & 31) == 0) red[tid >> 5] = sum;
    __syncthreads();
    if (tid == 0) out[b] = red[0] + red[1] + red[2] + red[3];
}

// ---------------------------------------------------------------------------
extern "C" void kernel_launch(void* const* d_in, const int* in_sizes, int n_in,
                              void* d_out, int out_size) {
    const float* parts = (const float*)d_in[0];
    const float* projs = (const float*)d_in[1];
    // d_in[2] (bins) unused: rings recomputed exactly (matches np.round).
    // d_in[3] (valid_mask) unused: mask == (3 < bin < 256), folded analytically.
    float* out = (float*)d_out;

    const int smem = WIN * Bn * (int)sizeof(float2)
                   + 4 * 32 * BPITCH * (int)sizeof(float)
                   + (TR * TC + WIN) * (int)sizeof(int);  // 56464 B
    cudaFuncSetAttribute(pass1_kernel,
                         cudaFuncAttributeMaxDynamicSharedMemorySize, smem);

    zero_kernel<<<1, NRING>>>();                          // launch 0
    noop_kernel<<<1, 32>>>();                             // launch 1
    noop_kernel<<<1, 32>>>();                             // launch 2
    pass1_kernel<<<NTILES, 128, smem>>>(parts, projs);    // launch 3 <- ncu
    pass3_kernel<<<Bn, 128>>>(out);                       // launch 4
}